// round 17
// baseline (speedup 1.0000x reference)
#include <cuda_runtime.h>
#include <cuda_fp16.h>
#include <cstdint>
#include <cstddef>

#define Bc    2
#define Tc    2048
#define Dc    2048
#define Hc    16
#define KEYD  2048
#define VALD  2048
#define CONVD 6144
#define BT    4096   // B*T
#define NCAT  8320   // 6144 qkv | 2048 z | 32 ab | 96 pad

typedef unsigned short u16;
typedef uint32_t u32;

// ---------------- scratch (device globals: allocation-free, zero-init) -------
__device__ float g_mx[(size_t)BT * NCAT];       // fused projection output
__device__ float g_qkv[(size_t)BT * CONVD];     // post conv+silu+l2norm
__device__ float g_od[(size_t)BT * VALD];       // delta-rule output

__device__ u16 g_hsA[(size_t)BT * Dc];
__device__ u16 g_Wcat[(size_t)NCAT * Dc];       // rows 8224.. stay zero
__device__ u16 g_Wo[(size_t)Dc * VALD];
__device__ u16 g_y[(size_t)BT * VALD];

// ---------------- helpers ----------------
__device__ __forceinline__ u16 h16bits(float x) {
    __half h = __float2half_rn(x);
    return *reinterpret_cast<u16*>(&h);
}
__device__ __forceinline__ u32 smem_u32(const void* p) {
    u32 a;
    asm("{ .reg .u64 t; cvta.to.shared.u64 t, %1; cvt.u32.u64 %0, t; }" : "=r"(a) : "l"(p));
    return a;
}
#define SWZ(x) ((x) ^ (((x) >> 3) & 0x70))

__device__ __forceinline__ void cp16(u32 s, const void* g) {
    asm volatile("cp.async.cg.shared.global [%0], [%1], 16;" :: "r"(s), "l"(g));
}
__device__ __forceinline__ void ldsm4(u32* r, u32 a) {
    asm volatile("ldmatrix.sync.aligned.m8n8.x4.shared.b16 {%0,%1,%2,%3}, [%4];"
                 : "=r"(r[0]), "=r"(r[1]), "=r"(r[2]), "=r"(r[3]) : "r"(a));
}
__device__ __forceinline__ void mma16816(float* c, const u32* a, const u32* b) {
    asm volatile(
        "mma.sync.aligned.m16n8k16.row.col.f32.f16.f16.f32 "
        "{%0,%1,%2,%3}, {%4,%5,%6,%7}, {%8,%9}, {%0,%1,%2,%3};"
        : "+f"(c[0]), "+f"(c[1]), "+f"(c[2]), "+f"(c[3])
        : "r"(a[0]), "r"(a[1]), "r"(a[2]), "r"(a[3]), "r"(b[0]), "r"(b[1]));
}

// ---------------- merged prep: cvt(hs) + transpose(Wqkv|Wz) + transpose(ab) --
#define PREP_CVT_B   8192
#define PREP_CAT_B   16384
#define PREP_AB_B    256
__global__ void prep_all_kernel(const float4* __restrict__ hs4,
                                ushort4* __restrict__ hsA4,
                                const float* __restrict__ Wqkv,
                                const float* __restrict__ Wz,
                                const float* __restrict__ Wa,
                                const float* __restrict__ Wb,
                                u16* __restrict__ Wcat) {
    __shared__ float t[32][33];
    const int blk = blockIdx.x;
    const int tid = threadIdx.y * 32 + threadIdx.x;   // 256
    if (blk < PREP_CVT_B) {
        int i = blk * 256 + tid;
        float4 v = hs4[i];
        ushort4 H;
        H.x = h16bits(v.x); H.y = h16bits(v.y);
        H.z = h16bits(v.z); H.w = h16bits(v.w);
        hsA4[i] = H;
    } else if (blk < PREP_CVT_B + PREP_CAT_B) {
        int b1 = blk - PREP_CVT_B;
        int n0g = (b1 & 255) * 32;
        int k0 = (b1 >> 8) * 32;
        const float* W; int N; int n0;
        if (n0g < CONVD) { W = Wqkv; N = CONVD; n0 = n0g; }
        else             { W = Wz;   N = VALD;  n0 = n0g - CONVD; }
        int x = threadIdx.x, y = threadIdx.y;
#pragma unroll
        for (int i = 0; i < 4; ++i)
            t[y + 8 * i][x] = W[(size_t)(k0 + y + 8 * i) * N + n0 + x];
        __syncthreads();
#pragma unroll
        for (int i = 0; i < 4; ++i)
            Wcat[(size_t)(n0g + y + 8 * i) * Dc + k0 + x] = h16bits(t[x][y + 8 * i]);
    } else {
        int b2 = blk - PREP_CVT_B - PREP_CAT_B;
        int n = b2 >> 3;
        int k = (b2 & 7) * 256 + tid;
        const float* W = (n < 16) ? Wa : Wb;
        Wcat[(size_t)(8192 + n) * Dc + k] = h16bits(W[(size_t)k * Hc + (n & 15)]);
    }
}

// W_out transpose
__global__ void transpose_cvt_kernel(const float* __restrict__ W,
                                     u16* __restrict__ Th, int Kd, int N) {
    __shared__ float t[32][33];
    int n0 = blockIdx.x * 32, k0 = blockIdx.y * 32;
    int x = threadIdx.x, y = threadIdx.y;
#pragma unroll
    for (int i = 0; i < 4; ++i)
        t[y + 8 * i][x] = W[(size_t)(k0 + y + 8 * i) * N + n0 + x];
    __syncthreads();
#pragma unroll
    for (int i = 0; i < 4; ++i)
        Th[(size_t)(n0 + y + 8 * i) * Kd + k0 + x] = h16bits(t[x][y + 8 * i]);
}

// ---------------- HMMA GEMM: C[M,N] = A[M,K] @ Bt[N,K]^T ----------------
__global__ __launch_bounds__(256, 2)
void mma_gemm(const u16* __restrict__ A, const u16* __restrict__ Bt,
              float* __restrict__ C, int M, int N, int Kd) {
    extern __shared__ __align__(1024) char smem[];
    constexpr int ATILE = 128 * 128;
    constexpr int STAGE = 2 * ATILE;
    constexpr int MF = 4;
    constexpr int NG = 2;
    const int tid = threadIdx.x, lane = tid & 31, wid = tid >> 5;
    const int wm = (wid & 1) * 64;
    const int wn = (wid >> 1) * 32;
    const int m0 = blockIdx.y * 128, n0 = blockIdx.x * 128;
    const int ktiles = Kd >> 6;
    const u32 sb = smem_u32(smem);

    const u16* Ag = A + (size_t)m0 * Kd;
    const u16* Bg = Bt + (size_t)n0 * Kd;

    auto issue = [&](int kt) {
        const int ko = kt << 6;
        const u32 st = sb + (u32)(kt % 3) * STAGE;
        for (int c = tid; c < 128 * 8; c += 256) {
            int rr = c >> 3, u = c & 7;
            cp16(st + SWZ(rr * 128 + u * 16), Ag + (size_t)rr * Kd + ko + u * 8);
            cp16(st + ATILE + SWZ(rr * 128 + u * 16), Bg + (size_t)rr * Kd + ko + u * 8);
        }
    };

    float acc[MF][4][4];
#pragma unroll
    for (int i = 0; i < MF; ++i)
#pragma unroll
        for (int j = 0; j < 4; ++j)
#pragma unroll
            for (int l = 0; l < 4; ++l) acc[i][j][l] = 0.f;

    issue(0);
    asm volatile("cp.async.commit_group;");
    issue(1);
    asm volatile("cp.async.commit_group;");

    for (int kt = 0; kt < ktiles; ++kt) {
        asm volatile("cp.async.wait_group 1;" ::: "memory");
        __syncthreads();
        if (kt + 2 < ktiles) issue(kt + 2);
        asm volatile("cp.async.commit_group;");

        const u32 Ab = sb + (u32)(kt % 3) * STAGE;
        const u32 Bb = Ab + ATILE;
#pragma unroll
        for (int ks = 0; ks < 4; ++ks) {
            u32 ah[MF][4], bh[NG][4];
            const int arow = wm + (lane & 15);
            const int acol = ks * 32 + ((lane >> 4) << 4);
#pragma unroll
            for (int mf = 0; mf < MF; ++mf)
                ldsm4(ah[mf], Ab + SWZ((arow + mf * 16) * 128 + acol));
            const int brow = wn + (lane & 7) + ((lane >> 4) << 3);
            const int bcol = ks * 32 + ((lane & 8) << 1);
#pragma unroll
            for (int g = 0; g < NG; ++g)
                ldsm4(bh[g], Bb + SWZ((brow + g * 16) * 128 + bcol));
#pragma unroll
            for (int mf = 0; mf < MF; ++mf)
#pragma unroll
                for (int g = 0; g < NG; ++g) {
                    mma16816(acc[mf][2 * g + 0], ah[mf], &bh[g][0]);
                    mma16816(acc[mf][2 * g + 1], ah[mf], &bh[g][2]);
                }
        }
    }

#pragma unroll
    for (int mf = 0; mf < MF; ++mf)
#pragma unroll
        for (int f = 0; f < 4; ++f) {
            int row = m0 + wm + mf * 16 + (lane >> 2);
            int col = n0 + wn + f * 8 + (lane & 3) * 2;
            float2 lo2, hi2;
            lo2.x = acc[mf][f][0]; lo2.y = acc[mf][f][1];
            hi2.x = acc[mf][f][2]; hi2.y = acc[mf][f][3];
            *(float2*)&C[(size_t)row * N + col] = lo2;
            *(float2*)&C[(size_t)(row + 8) * N + col] = hi2;
        }
}

// ---------- depthwise causal conv (K=4) + silu + fused per-head L2 norm ------
__global__ __launch_bounds__(128)
void conv_silu_norm_kernel(const float* __restrict__ mx,
                           const float* __restrict__ cw,
                           float* __restrict__ out) {
    __shared__ float sm[128 * 33];
    __shared__ float ssum[4][32];
    __shared__ float sscale[32];
    const int tid = threadIdx.x;
    const int xb = blockIdx.x;
    const int c  = xb * 128 + tid;
    const int b  = blockIdx.z;
    const int t0 = blockIdx.y * 256;
    const bool qk = (xb < 32);
    const float qs = (xb < 16) ? 0.08838834764831845f : 1.f;
    const float w0 = cw[c * 4 + 0], w1 = cw[c * 4 + 1];
    const float w2 = cw[c * 4 + 2], w3 = cw[c * 4 + 3];
    const float* base  = mx  + (size_t)b * Tc * NCAT + c;
    float*       obase = out + (size_t)b * Tc * CONVD + c;
    float xm3 = (t0 >= 3) ? base[(size_t)(t0 - 3) * NCAT] : 0.f;
    float xm2 = (t0 >= 2) ? base[(size_t)(t0 - 2) * NCAT] : 0.f;
    float xm1 = (t0 >= 1) ? base[(size_t)(t0 - 1) * NCAT] : 0.f;

    for (int tile = 0; tile < 8; ++tile) {
        const int tb = t0 + tile * 32;
        float yv[32];
#pragma unroll
        for (int u = 0; u < 32; ++u) {
            float x = base[(size_t)(tb + u) * NCAT];
            float y = fmaf(w0, xm3, fmaf(w1, xm2, fmaf(w2, xm1, w3 * x)));
            yv[u] = y / (1.f + expf(-y));
            xm3 = xm2; xm2 = xm1; xm1 = x;
        }
        if (qk) {
#pragma unroll
            for (int u = 0; u < 32; ++u) sm[tid * 33 + u] = yv[u];
            __syncthreads();
            const int tl = tid & 31, grp = tid >> 5;
            float ss = 0.f;
#pragma unroll
            for (int i = 0; i < 32; ++i) {
                float v = sm[(grp * 32 + i) * 33 + tl];
                ss = fmaf(v, v, ss);
            }
            ssum[grp][tl] = ss;
            __syncthreads();
            if (tid < 32)
                sscale[tid] = rsqrtf(ssum[0][tid] + ssum[1][tid] +
                                     ssum[2][tid] + ssum[3][tid] + 1e-6f) * qs;
            __syncthreads();
#pragma unroll
            for (int u = 0; u < 32; ++u)
                obase[(size_t)(tb + u) * CONVD] = yv[u] * sscale[u];
            __syncthreads();
        } else {
#pragma unroll
            for (int u = 0; u < 32; ++u)
                obase[(size_t)(tb + u) * CONVD] = yv[u];
        }
    }
}

// ---------------- gated delta rule scan (+fused a/b activation) -------------
// 512 threads: tk in [0,16) owns 8 k's; tv in [0,32) owns ONE v-column.
// 16 warps/SM for issue/latency coverage. Prefetch depth 2 (double-buffered).
__global__ __launch_bounds__(512, 1)
void scan_kernel(const float* __restrict__ qkv, const float* __restrict__ mx,
                 const float* __restrict__ dt_bias, const float* __restrict__ A_log,
                 float* __restrict__ od) {
    __shared__ float sg[Tc];
    __shared__ float sbeta[Tc];
    const int blk  = blockIdx.x;
    const int vblk = blk & 3;
    const int h    = (blk >> 2) & 15;
    const int b    = blk >> 6;
    const int tid = threadIdx.x;
    const int tk = tid & 15, tv = tid >> 4;   // tv 0..31
    const int vcol = vblk * 32 + tv;

    // fused a/b activation for this (b,h)
    {
        const float dtb = dt_bias[h];
        const float nA = -expf(A_log[h]);
        const float* mxa = mx + (size_t)b * Tc * NCAT + 8192 + h;
        for (int t = tid; t < Tc; t += 512) {
            float av = mxa[(size_t)t * NCAT];
            float bv = mxa[(size_t)t * NCAT + 16];
            float x = av + dtb;
            float sp = (x > 20.f) ? x : log1pf(expf(x));
            sg[t] = nA * sp;
            sbeta[t] = 1.f / (1.f + expf(-bv));
        }
        __syncthreads();
    }

    const float* qp = qkv + (size_t)b * Tc * CONVD + h * 128 + tk * 8;
    const float* kp = qp + KEYD;
    const float* vp = qkv + (size_t)b * Tc * CONVD + 2 * KEYD + h * 128 + vcol;
    float* op = od + ((size_t)b * Tc * Hc + h) * 128 + vcol;

    float S[8];
#pragma unroll
    for (int i = 0; i < 8; ++i) S[i] = 0.f;

    float QA[2][8], KA[2][8], VA[2];
    float QB[2][8], KB[2][8], VB[2];
    int tg = 0;

#define LOADG(Q, K, V, pred)                                                 \
    {                                                                        \
        if (pred) {                                                          \
            _Pragma("unroll")                                                \
            for (int u = 0; u < 2; ++u) {                                    \
                float4 q0 = *(const float4*)(qp + (size_t)u * CONVD);        \
                float4 q1 = *(const float4*)(qp + (size_t)u * CONVD + 4);    \
                float4 k0 = *(const float4*)(kp + (size_t)u * CONVD);        \
                float4 k1 = *(const float4*)(kp + (size_t)u * CONVD + 4);    \
                V[u] = vp[(size_t)u * CONVD];                                \
                Q[u][0] = q0.x; Q[u][1] = q0.y; Q[u][2] = q0.z; Q[u][3] = q0.w; \
                Q[u][4] = q1.x; Q[u][5] = q1.y; Q[u][6] = q1.z; Q[u][7] = q1.w; \
                K[u][0] = k0.x; K[u][1] = k0.y; K[u][2] = k0.z; K[u][3] = k0.w; \
                K[u][4] = k1.x; K[u][5] = k1.y; K[u][6] = k1.z; K[u][7] = k1.w; \
            }                                                                \
        }                                                                    \
        qp += 2 * CONVD; kp += 2 * CONVD; vp += 2 * CONVD;                   \
    }

#define COMPG(Q, K, V)                                                       \
    {                                                                        \
        float eg2[2], bb2[2];                                                \
        _Pragma("unroll")                                                    \
        for (int u = 0; u < 2; ++u) {                                        \
            eg2[u] = __expf(sg[tg + u]);                                     \
            bb2[u] = sbeta[tg + u];                                          \
        }                                                                    \
        float OS[2];                                                         \
        _Pragma("unroll")                                                    \
        for (int u = 0; u < 2; ++u) {                                        \
            const float eg = eg2[u], bb = bb2[u];                            \
            float ks = 0.f;                                                  \
            _Pragma("unroll")                                                \
            for (int i = 0; i < 8; ++i) ks = fmaf(K[u][i], S[i], ks);        \
            _Pragma("unroll")                                                \
            for (int off = 8; off; off >>= 1)                                \
                ks += __shfl_xor_sync(~0u, ks, off);                         \
            float d = (V[u] - eg * ks) * bb;                                 \
            float os = 0.f;                                                  \
            _Pragma("unroll")                                                \
            for (int i = 0; i < 8; ++i) {                                    \
                S[i] = fmaf(K[u][i], d, eg * S[i]);                          \
                os = fmaf(Q[u][i], S[i], os);                                \
            }                                                                \
            OS[u] = os;                                                      \
        }                                                                    \
        _Pragma("unroll")                                                    \
        for (int off = 8; off; off >>= 1) {                                  \
            OS[0] += __shfl_xor_sync(~0u, OS[0], off);                       \
            OS[1] += __shfl_xor_sync(~0u, OS[1], off);                       \
        }                                                                    \
        if (tk == 0) {                                                       \
            op[0] = OS[0];                                                   \
            op[(size_t)Hc * 128] = OS[1];                                    \
        }                                                                    \
        op += (size_t)2 * Hc * 128;                                          \
        tg += 2;                                                             \
    }

    LOADG(QA, KA, VA, true);
    for (int t = 0; t < Tc; t += 4) {
        LOADG(QB, KB, VB, true);
        COMPG(QA, KA, VA);
        bool pr = (t + 4) < Tc;
        LOADG(QA, KA, VA, pr);
        COMPG(QB, KB, VB);
    }
#undef LOADG
#undef COMPG
}

// ---------------- gated RMSNorm -> fp16 (z from fused buffer) ----------------
__global__ void gate_norm_kernel(const float* __restrict__ od,
                                 const float* __restrict__ mx,
                                 const float* __restrict__ nw,
                                 ushort4* __restrict__ y) {
    const int warp = threadIdx.x >> 5, lane = threadIdx.x & 31;
    const int vec = blockIdx.x * 8 + warp;
    const float* opv = od + (size_t)vec * 128 + lane * 4;
    const float* zpv = mx + (size_t)(vec >> 4) * NCAT + 6144 + (vec & 15) * 128 + lane * 4;
    float4 o  = *(const float4*)opv;
    float4 zz = *(const float4*)zpv;
    float4 og;
    og.x = o.x * (zz.x / (1.f + expf(-zz.x)));
    og.y = o.y * (zz.y / (1.f + expf(-zz.y)));
    og.z = o.z * (zz.z / (1.f + expf(-zz.z)));
    og.w = o.w * (zz.w / (1.f + expf(-zz.w)));
    float ss = og.x * og.x + og.y * og.y + og.z * og.z + og.w * og.w;
#pragma unroll
    for (int off = 16; off; off >>= 1) ss += __shfl_xor_sync(~0u, ss, off);
    float r = rsqrtf(ss * (1.f / 128.f) + 1e-6f);
    float4 w = *(const float4*)&nw[lane * 4];
    ushort4 H;
    H.x = h16bits(og.x * r * w.x);
    H.y = h16bits(og.y * r * w.y);
    H.z = h16bits(og.z * r * w.z);
    H.w = h16bits(og.w * r * w.w);
    y[(size_t)vec * 32 + lane] = H;
}

// ---------------- launch ----------------
extern "C" void kernel_launch(void* const* d_in, const int* in_sizes, int n_in,
                              void* d_out, int out_size) {
    const float* hs      = (const float*)d_in[0];
    const float* W_qkv   = (const float*)d_in[1];
    const float* conv_w  = (const float*)d_in[2];
    const float* W_z     = (const float*)d_in[3];
    const float* W_b     = (const float*)d_in[4];
    const float* W_a     = (const float*)d_in[5];
    const float* dt_bias = (const float*)d_in[6];
    const float* A_log   = (const float*)d_in[7];
    const float* norm_w  = (const float*)d_in[8];
    const float* W_out   = (const float*)d_in[9];
    float* out = (float*)d_out;

    float *mx, *qkv, *od;
    u16 *hsA, *Wcat, *Wo, *y;
    cudaGetSymbolAddress((void**)&mx,   g_mx);
    cudaGetSymbolAddress((void**)&qkv,  g_qkv);
    cudaGetSymbolAddress((void**)&od,   g_od);
    cudaGetSymbolAddress((void**)&hsA,  g_hsA);
    cudaGetSymbolAddress((void**)&Wcat, g_Wcat);
    cudaGetSymbolAddress((void**)&Wo,   g_Wo);
    cudaGetSymbolAddress((void**)&y,    g_y);

    const int smemG = 3 * (16384 + 16384);   // 98304
    cudaFuncSetAttribute(mma_gemm, cudaFuncAttributeMaxDynamicSharedMemorySize, smemG);

    // 1. merged prep
    prep_all_kernel<<<PREP_CVT_B + PREP_CAT_B + PREP_AB_B, dim3(32, 8)>>>(
        (const float4*)hs, (ushort4*)hsA, W_qkv, W_z, W_a, W_b, Wcat);
    // 2. fused projections
    mma_gemm<<<dim3(NCAT / 128, BT / 128), 256, smemG>>>(hsA, Wcat, mx, BT, NCAT, Dc);
    // 3. conv + silu + fused l2norm
    conv_silu_norm_kernel<<<dim3(CONVD / 128, Tc / 256, Bc), 128>>>(mx, conv_w, qkv);
    // 4. gated delta rule scan  <-- PROFILED SLOT
    scan_kernel<<<Bc * Hc * 4, 512>>>(qkv, mx, dt_bias, A_log, od);
    // 5. W_out transpose
    transpose_cvt_kernel<<<dim3(Dc / 32, VALD / 32), dim3(32, 8)>>>(W_out, Wo, VALD, Dc);
    // 6. gated RMSNorm -> y fp16
    gate_norm_kernel<<<(BT * Hc) / 8, 256>>>(od, mx, norm_w, (ushort4*)y);
    // 7. out = y @ W_out
    mma_gemm<<<dim3(Dc / 128, BT / 128), 256, smemG>>>(y, Wo, out, BT, Dc, Dc);
}